// round 1
// baseline (speedup 1.0000x reference)
#include <cuda_runtime.h>
#include <cuda_bf16.h>
#include <cstdint>

#define N_ROWS 8192
#define DIM    512
#define INV_T  (1.0f / 0.07f)

#define TM 128
#define TN 128
#define KC 64
#define JSPLIT 8
#define JT_PER (N_ROWS / TN / JSPLIT)   // 8 j-tiles per CTA

// ---------------- scratch (no allocs allowed) ----------------
__device__ __align__(16) __nv_bfloat16 g_Hn[N_ROWS * DIM];   // normalized, bf16
__device__ float g_total[N_ROWS];
__device__ float g_pos[N_ROWS];
__device__ int   g_hist[128];
__device__ int   g_lab[N_ROWS];
__device__ int   g_is64;

// ---------------- zero scratch ----------------
__global__ void k_zero() {
    int i = blockIdx.x * blockDim.x + threadIdx.x;
    if (i < N_ROWS) { g_total[i] = 0.f; g_pos[i] = 0.f; }
    if (i < 128) g_hist[i] = 0;
}

// ---------------- detect label dtype (int32 vs int64) ----------------
__global__ void k_detect(const int* lab32) {
    int odd_nonzero = 0;
    for (int i = 0; i < 32; i++)
        if (lab32[2 * i + 1] != 0) odd_nonzero++;
    g_is64 = (odd_nonzero == 0) ? 1 : 0;
}

// ---------------- label histogram + int cast ----------------
__global__ void k_hist(const void* labels) {
    int i = blockIdx.x * blockDim.x + threadIdx.x;
    if (i < N_ROWS) {
        int l = g_is64 ? (int)((const long long*)labels)[i]
                       : ((const int*)labels)[i];
        l &= 127;  // safety clamp (labels are 0..99)
        g_lab[i] = l;
        atomicAdd(&g_hist[l], 1);
    }
}

// ---------------- L2-normalize rows, emit bf16 ----------------
__global__ void k_normalize(const float* __restrict__ hidden) {
    int row = blockIdx.x;
    const float4* src = reinterpret_cast<const float4*>(hidden + (size_t)row * DIM);
    float4 v = src[threadIdx.x];
    float ss = v.x * v.x + v.y * v.y + v.z * v.z + v.w * v.w;
    #pragma unroll
    for (int o = 16; o; o >>= 1) ss += __shfl_xor_sync(~0u, ss, o);
    __shared__ float s[4];
    if ((threadIdx.x & 31) == 0) s[threadIdx.x >> 5] = ss;
    __syncthreads();
    float tot = s[0] + s[1] + s[2] + s[3];
    float inv = 1.0f / fmaxf(sqrtf(tot), 1e-12f);
    __nv_bfloat162 p0 = __floats2bfloat162_rn(v.x * inv, v.y * inv);
    __nv_bfloat162 p1 = __floats2bfloat162_rn(v.z * inv, v.w * inv);
    __nv_bfloat162* dst = reinterpret_cast<__nv_bfloat162*>(g_Hn + (size_t)row * DIM) + threadIdx.x * 2;
    dst[0] = p0; dst[1] = p1;
}

// ---------------- fused GEMM + exp/mask/row-sum epilogue ----------------
__global__ void __launch_bounds__(256, 2) k_gemm() {
    __shared__ __align__(16) __nv_bfloat16 sA[TM][KC + 8];
    __shared__ __align__(16) __nv_bfloat16 sB[TN][KC + 8];
    __shared__ float s_tot[TM], s_pos[TM];
    __shared__ int   s_labI[TM], s_labJ[TN];

    int tid  = threadIdx.x;
    int lane = tid & 31, warp = tid >> 5;
    int wm = warp >> 1, wn = warp & 1;     // 4x2 warp grid over 128x128 C
    int i0 = blockIdx.x * TM;

    if (tid < TM) {
        s_tot[tid] = 0.f; s_pos[tid] = 0.f;
        s_labI[tid] = g_lab[i0 + tid];
    }

    float acc[2][8][4];

    for (int jj = 0; jj < JT_PER; ++jj) {
        int j0 = (blockIdx.y * JT_PER + jj) * TN;
        __syncthreads();                      // prev epilogue done before labJ rewrite
        if (tid < TN) s_labJ[tid] = g_lab[j0 + tid];

        #pragma unroll
        for (int mi = 0; mi < 2; mi++)
            #pragma unroll
            for (int ni = 0; ni < 8; ni++)
                #pragma unroll
                for (int e = 0; e < 4; e++) acc[mi][ni][e] = 0.f;

        for (int kc = 0; kc < DIM; kc += KC) {
            __syncthreads();                  // prev ldmatrix reads done
            const uint4* gH = reinterpret_cast<const uint4*>(g_Hn);
            #pragma unroll
            for (int u = 0; u < 4; u++) {
                int q = tid + u * 256;        // 0..1023 -> 128 rows x 8 uint4
                int r = q >> 3, c16 = q & 7;
                uint4 val = gH[((i0 + r) * DIM + kc) / 8 + c16];
                *reinterpret_cast<uint4*>(&sA[r][c16 * 8]) = val;
            }
            #pragma unroll
            for (int u = 0; u < 4; u++) {
                int q = tid + u * 256;
                int r = q >> 3, c16 = q & 7;
                uint4 val = gH[((j0 + r) * DIM + kc) / 8 + c16];
                *reinterpret_cast<uint4*>(&sB[r][c16 * 8]) = val;
            }
            __syncthreads();

            #pragma unroll
            for (int ks = 0; ks < KC; ks += 16) {
                uint32_t a[2][4];
                #pragma unroll
                for (int mi = 0; mi < 2; mi++) {
                    unsigned addr = (unsigned)__cvta_generic_to_shared(
                        &sA[wm * 32 + mi * 16 + (lane & 15)][ks + (lane >> 4) * 8]);
                    asm volatile("ldmatrix.sync.aligned.m8n8.x4.shared.b16 {%0,%1,%2,%3}, [%4];\n"
                        : "=r"(a[mi][0]), "=r"(a[mi][1]), "=r"(a[mi][2]), "=r"(a[mi][3])
                        : "r"(addr));
                }
                uint32_t b[8][2];
                #pragma unroll
                for (int nb = 0; nb < 4; nb++) {
                    // 4 matrices: (n 0-7,k0-7), (n 0-7,k8-15), (n 8-15,k0-7), (n 8-15,k8-15)
                    unsigned addr = (unsigned)__cvta_generic_to_shared(
                        &sB[wn * 64 + nb * 16 + (lane >> 4) * 8 + (lane & 7)]
                           [ks + ((lane >> 3) & 1) * 8]);
                    asm volatile("ldmatrix.sync.aligned.m8n8.x4.shared.b16 {%0,%1,%2,%3}, [%4];\n"
                        : "=r"(b[2 * nb][0]), "=r"(b[2 * nb][1]),
                          "=r"(b[2 * nb + 1][0]), "=r"(b[2 * nb + 1][1])
                        : "r"(addr));
                }
                #pragma unroll
                for (int mi = 0; mi < 2; mi++)
                    #pragma unroll
                    for (int ni = 0; ni < 8; ni++)
                        asm volatile(
                            "mma.sync.aligned.m16n8k16.row.col.f32.bf16.bf16.f32 "
                            "{%0,%1,%2,%3},{%4,%5,%6,%7},{%8,%9},{%0,%1,%2,%3};\n"
                            : "+f"(acc[mi][ni][0]), "+f"(acc[mi][ni][1]),
                              "+f"(acc[mi][ni][2]), "+f"(acc[mi][ni][3])
                            : "r"(a[mi][0]), "r"(a[mi][1]), "r"(a[mi][2]), "r"(a[mi][3]),
                              "r"(b[ni][0]), "r"(b[ni][1]));
            }
        }

        // ---- epilogue: exp + masks + row-partial sums (diag excluded, added exactly later) ----
        #pragma unroll
        for (int mi = 0; mi < 2; mi++) {
            #pragma unroll
            for (int v = 0; v < 2; v++) {
                int rl = wm * 32 + mi * 16 + (lane >> 2) + v * 8;
                int gi = i0 + rl;
                int li = s_labI[rl];
                float sT = 0.f, sP = 0.f;
                #pragma unroll
                for (int ni = 0; ni < 8; ni++) {
                    #pragma unroll
                    for (int e = 0; e < 2; e++) {
                        int cl = wn * 64 + ni * 8 + (lane & 3) * 2 + e;
                        int gj = j0 + cl;
                        float c = acc[mi][ni][v * 2 + e];
                        float ev = __expf(c * INV_T);
                        if (gj != gi) {
                            sT += ev;
                            if (s_labJ[cl] == li) sP += ev;
                        }
                    }
                }
                sT += __shfl_xor_sync(~0u, sT, 1); sP += __shfl_xor_sync(~0u, sP, 1);
                sT += __shfl_xor_sync(~0u, sT, 2); sP += __shfl_xor_sync(~0u, sP, 2);
                if ((lane & 3) == 0) {
                    atomicAdd(&s_tot[rl], sT);
                    atomicAdd(&s_pos[rl], sP);
                }
            }
        }
    }
    __syncthreads();
    if (tid < TM) {
        atomicAdd(&g_total[i0 + tid], s_tot[tid]);
        atomicAdd(&g_pos[i0 + tid], s_pos[tid]);
    }
}

// ---------------- final reduction ----------------
__global__ void k_finalize(float* out) {
    __shared__ float red[256];
    float s = 0.f;
    for (int i = threadIdx.x; i < N_ROWS; i += 256) {
        float tot = g_total[i] + expf(INV_T);          // exact diagonal term
        float cnt = (float)(g_hist[g_lab[i]] - 1);
        float ps  = g_pos[i] / (cnt + 1e-9f);
        s += logf(ps / tot);
    }
    red[threadIdx.x] = s;
    __syncthreads();
    for (int o = 128; o; o >>= 1) {
        if (threadIdx.x < o) red[threadIdx.x] += red[threadIdx.x + o];
        __syncthreads();
    }
    if (threadIdx.x == 0) out[0] = -red[0] / (float)N_ROWS;
}

extern "C" void kernel_launch(void* const* d_in, const int* in_sizes, int n_in,
                              void* d_out, int out_size) {
    const float* hidden = (const float*)d_in[0];
    const void*  labels = d_in[1];

    k_zero<<<32, 256>>>();
    k_detect<<<1, 1>>>((const int*)labels);
    k_normalize<<<N_ROWS, 128>>>(hidden);
    k_hist<<<32, 256>>>(labels);
    k_gemm<<<dim3(N_ROWS / TM, JSPLIT), 256>>>();
    k_finalize<<<1, 256>>>((float*)d_out);
}

// round 3
// speedup vs baseline: 3.1000x; 3.1000x over previous
#include <cuda_runtime.h>
#include <cuda_bf16.h>
#include <cstdint>

#define N_ROWS 8192
#define DIM    512
#define INV_T  (1.0f / 0.07f)

#define TM 128
#define TN 128
#define KC 64
#define NK (DIM / KC)            // 8 K-chunks
#define NTI (N_ROWS / TM)        // 64 tile-rows
#define NTILE (NTI * (NTI + 1) / 2)   // 2080 upper-triangle tiles
#define STAGE_BYTES ((TM + TN) * KC * 2)   // 32 KB
#define NSTAGE 3
#define SMEM_DYN (NSTAGE * STAGE_BYTES)    // 96 KB

// ---------------- scratch (no allocs allowed) ----------------
__device__ __align__(16) __nv_bfloat16 g_Hn[N_ROWS * DIM];   // normalized, bf16, row-major
__device__ float g_total[N_ROWS];
__device__ float g_pos[N_ROWS];
__device__ int   g_hist[128];
__device__ int   g_lab[N_ROWS];
__device__ int   g_is64;

// ---------------- zero scratch ----------------
__global__ void k_zero() {
    int i = blockIdx.x * blockDim.x + threadIdx.x;
    if (i < N_ROWS) { g_total[i] = 0.f; g_pos[i] = 0.f; }
    if (i < 128) g_hist[i] = 0;
}

// ---------------- detect label dtype (int32 vs int64) ----------------
__global__ void k_detect(const int* lab32) {
    int odd_nonzero = 0;
    for (int i = 0; i < 32; i++)
        if (lab32[2 * i + 1] != 0) odd_nonzero++;
    g_is64 = (odd_nonzero == 0) ? 1 : 0;
}

// ---------------- label histogram + int cast ----------------
__global__ void k_hist(const void* labels) {
    int i = blockIdx.x * blockDim.x + threadIdx.x;
    if (i < N_ROWS) {
        int l = g_is64 ? (int)((const long long*)labels)[i]
                       : ((const int*)labels)[i];
        l &= 127;
        g_lab[i] = l;
        atomicAdd(&g_hist[l], 1);
    }
}

// ---------------- L2-normalize rows, emit bf16 ----------------
__global__ void k_normalize(const float* __restrict__ hidden) {
    int row = blockIdx.x;
    const float4* src = reinterpret_cast<const float4*>(hidden + (size_t)row * DIM);
    float4 v = src[threadIdx.x];
    float ss = v.x * v.x + v.y * v.y + v.z * v.z + v.w * v.w;
    #pragma unroll
    for (int o = 16; o; o >>= 1) ss += __shfl_xor_sync(~0u, ss, o);
    __shared__ float s[4];
    if ((threadIdx.x & 31) == 0) s[threadIdx.x >> 5] = ss;
    __syncthreads();
    float tot = s[0] + s[1] + s[2] + s[3];
    float inv = 1.0f / fmaxf(sqrtf(tot), 1e-12f);
    __nv_bfloat162 p0 = __floats2bfloat162_rn(v.x * inv, v.y * inv);
    __nv_bfloat162 p1 = __floats2bfloat162_rn(v.z * inv, v.w * inv);
    uint2 pk;
    pk.x = *reinterpret_cast<uint32_t*>(&p0);
    pk.y = *reinterpret_cast<uint32_t*>(&p1);
    *reinterpret_cast<uint2*>((char*)g_Hn + (size_t)row * DIM * 2 + threadIdx.x * 8) = pk;
}

__device__ __forceinline__ uint32_t smem_u32(const void* p) {
    return (uint32_t)__cvta_generic_to_shared(p);
}
__device__ __forceinline__ void cp16(uint32_t dst, const void* src) {
    asm volatile("cp.async.cg.shared.global [%0], [%1], 16;" :: "r"(dst), "l"(src) : "memory");
}

// ---------------- symmetric-tile GEMM + fused epilogue ----------------
__global__ void __launch_bounds__(256, 2) k_gemm_sym() {
    extern __shared__ char smem[];
    __shared__ float s_colT[TN], s_colP[TN];
    __shared__ int   s_labI[TM], s_labJ[TN];

    const int tid  = threadIdx.x;
    const int lane = tid & 31, warp = tid >> 5;
    const int wm = warp >> 1, wn = warp & 1;   // 4x2 warps over 128x128

    // decode upper-triangle tile (ti <= tj); offset f(t) = t*(2*NTI+1-t)/2
    int bid = blockIdx.x;
    int ti = (int)((129.0f - sqrtf(129.0f * 129.0f - 8.0f * (float)bid)) * 0.5f);
    #define FOFF(t) ((t) * (2 * NTI + 1 - (t)) / 2)
    while (FOFF(ti + 1) <= bid) ti++;
    while (FOFF(ti) > bid) ti--;
    int tj = ti + (bid - FOFF(ti));
    const int i0 = ti * TM, j0 = tj * TN;
    const bool diag = (ti == tj);

    if (tid < TM) {
        s_labI[tid] = g_lab[i0 + tid];
        s_labJ[tid] = g_lab[j0 + tid];
        s_colT[tid] = 0.f; s_colP[tid] = 0.f;
    }

    // ---- cp.async tile loader: 128 rows x 8 x 16B per operand, XOR-swizzled ----
    auto load_stage = [&](int s, int k) {
        char* dA = smem + s * STAGE_BYTES;
        char* dB = dA + TM * KC * 2;
        const char* gA = (const char*)g_Hn + ((size_t)i0 * DIM + k * KC) * 2;
        const char* gB = (const char*)g_Hn + ((size_t)j0 * DIM + k * KC) * 2;
        #pragma unroll
        for (int u = 0; u < 4; u++) {
            int q = tid + u * 256;           // 0..1023
            int r = q >> 3, c = q & 7;
            uint32_t sw = (uint32_t)((c ^ (r & 7)) << 4);
            cp16(smem_u32(dA + r * 128 + sw), gA + (size_t)r * (DIM * 2) + c * 16);
            cp16(smem_u32(dB + r * 128 + sw), gB + (size_t)r * (DIM * 2) + c * 16);
        }
    };

    load_stage(0, 0);
    asm volatile("cp.async.commit_group;" ::: "memory");
    load_stage(1, 1);
    asm volatile("cp.async.commit_group;" ::: "memory");

    float acc[2][8][4];
    #pragma unroll
    for (int mi = 0; mi < 2; mi++)
        #pragma unroll
        for (int ni = 0; ni < 8; ni++)
            #pragma unroll
            for (int e = 0; e < 4; e++) acc[mi][ni][e] = 0.f;

    for (int k = 0; k < NK; k++) {
        __syncthreads();                          // all warps done with buf[(k+2)%3]
        if (k + 2 < NK) load_stage((k + 2) % NSTAGE, k + 2);
        asm volatile("cp.async.commit_group;" ::: "memory");
        asm volatile("cp.async.wait_group 2;" ::: "memory");
        __syncthreads();                          // stage k visible

        char* A = smem + (k % NSTAGE) * STAGE_BYTES;
        char* B = A + TM * KC * 2;
        #pragma unroll
        for (int ks = 0; ks < 4; ks++) {          // 4 x k16
            uint32_t a[2][4];
            #pragma unroll
            for (int mi = 0; mi < 2; mi++) {
                int r = wm * 32 + mi * 16 + (lane & 15);
                int ch = ks * 2 + (lane >> 4);
                uint32_t addr = smem_u32(A + r * 128 + ((ch ^ (r & 7)) << 4));
                asm volatile("ldmatrix.sync.aligned.m8n8.x4.shared.b16 {%0,%1,%2,%3}, [%4];\n"
                    : "=r"(a[mi][0]), "=r"(a[mi][1]), "=r"(a[mi][2]), "=r"(a[mi][3])
                    : "r"(addr));
            }
            uint32_t b[8][2];
            #pragma unroll
            for (int nb = 0; nb < 4; nb++) {
                int r = wn * 64 + nb * 16 + (lane >> 4) * 8 + (lane & 7);
                int ch = ks * 2 + ((lane >> 3) & 1);
                uint32_t addr = smem_u32(B + r * 128 + ((ch ^ (r & 7)) << 4));
                asm volatile("ldmatrix.sync.aligned.m8n8.x4.shared.b16 {%0,%1,%2,%3}, [%4];\n"
                    : "=r"(b[2 * nb][0]), "=r"(b[2 * nb][1]),
                      "=r"(b[2 * nb + 1][0]), "=r"(b[2 * nb + 1][1])
                    : "r"(addr));
            }
            #pragma unroll
            for (int mi = 0; mi < 2; mi++)
                #pragma unroll
                for (int ni = 0; ni < 8; ni++)
                    asm volatile(
                        "mma.sync.aligned.m16n8k16.row.col.f32.bf16.bf16.f32 "
                        "{%0,%1,%2,%3},{%4,%5,%6,%7},{%8,%9},{%0,%1,%2,%3};\n"
                        : "+f"(acc[mi][ni][0]), "+f"(acc[mi][ni][1]),
                          "+f"(acc[mi][ni][2]), "+f"(acc[mi][ni][3])
                        : "r"(a[mi][0]), "r"(a[mi][1]), "r"(a[mi][2]), "r"(a[mi][3]),
                          "r"(b[ni][0]), "r"(b[ni][1]));
        }
    }
    __syncthreads();

    // ---- epilogue: exp once, scatter to row sums (i) and column sums (j) ----
    float colT[16], colP[16];
    #pragma unroll
    for (int x = 0; x < 16; x++) { colT[x] = 0.f; colP[x] = 0.f; }

    #pragma unroll
    for (int mi = 0; mi < 2; mi++) {
        #pragma unroll
        for (int v = 0; v < 2; v++) {
            const int rl = wm * 32 + mi * 16 + (lane >> 2) + v * 8;
            const int li = s_labI[rl];
            float sT = 0.f, sP = 0.f;
            #pragma unroll
            for (int ni = 0; ni < 8; ni++) {
                #pragma unroll
                for (int e = 0; e < 2; e++) {
                    const int cl = wn * 64 + ni * 8 + (lane & 3) * 2 + e;
                    float ev = __expf(acc[mi][ni][v * 2 + e] * INV_T);
                    bool same = (s_labJ[cl] == li);
                    if (!(diag && rl == cl)) {
                        sT += ev;
                        if (same) sP += ev;
                        if (!diag) {
                            colT[ni * 2 + e] += ev;
                            if (same) colP[ni * 2 + e] += ev;
                        }
                    }
                }
            }
            sT += __shfl_xor_sync(~0u, sT, 1); sP += __shfl_xor_sync(~0u, sP, 1);
            sT += __shfl_xor_sync(~0u, sT, 2); sP += __shfl_xor_sync(~0u, sP, 2);
            if ((lane & 3) == 0) {
                atomicAdd(&g_total[i0 + rl], sT);
                atomicAdd(&g_pos[i0 + rl], sP);
            }
        }
    }

    if (!diag) {
        #pragma unroll
        for (int x = 0; x < 16; x++) {
            float cT = colT[x], cP = colP[x];
            cT += __shfl_xor_sync(~0u, cT, 4);  cP += __shfl_xor_sync(~0u, cP, 4);
            cT += __shfl_xor_sync(~0u, cT, 8);  cP += __shfl_xor_sync(~0u, cP, 8);
            cT += __shfl_xor_sync(~0u, cT, 16); cP += __shfl_xor_sync(~0u, cP, 16);
            if (lane < 4) {
                int cl = wn * 64 + (x >> 1) * 8 + lane * 2 + (x & 1);
                atomicAdd(&s_colT[cl], cT);
                atomicAdd(&s_colP[cl], cP);
            }
        }
        __syncthreads();
        if (tid < TN) {
            atomicAdd(&g_total[j0 + tid], s_colT[tid]);
            atomicAdd(&g_pos[j0 + tid], s_colP[tid]);
        }
    }
}

// ---------------- final reduction ----------------
__global__ void k_finalize(float* out) {
    __shared__ float red[256];
    float s = 0.f;
    for (int i = threadIdx.x; i < N_ROWS; i += 256) {
        float tot = g_total[i] + expf(INV_T);   // exact diagonal term
        float cnt = (float)(g_hist[g_lab[i]] - 1);
        float ps  = g_pos[i] / (cnt + 1e-9f);
        s += logf(ps / tot);
    }
    red[threadIdx.x] = s;
    __syncthreads();
    for (int o = 128; o; o >>= 1) {
        if (threadIdx.x < o) red[threadIdx.x] += red[threadIdx.x + o];
        __syncthreads();
    }
    if (threadIdx.x == 0) out[0] = -red[0] / (float)N_ROWS;
}

extern "C" void kernel_launch(void* const* d_in, const int* in_sizes, int n_in,
                              void* d_out, int out_size) {
    const float* hidden = (const float*)d_in[0];
    const void*  labels = d_in[1];

    cudaFuncSetAttribute(k_gemm_sym, cudaFuncAttributeMaxDynamicSharedMemorySize, SMEM_DYN);

    k_zero<<<32, 256>>>();
    k_detect<<<1, 1>>>((const int*)labels);
    k_normalize<<<N_ROWS, 128>>>(hidden);
    k_hist<<<32, 256>>>(labels);
    k_gemm_sym<<<NTILE, 256, SMEM_DYN>>>();
    k_finalize<<<1, 256>>>((float*)d_out);
}